// round 4
// baseline (speedup 1.0000x reference)
#include <cuda_runtime.h>
#include <cuda_bf16.h>

// BFP quant-dequant: shared 8-bit exponent per block of 8 along the last dim.
// x: [8192, 12284] fp32 -> out same shape.
//
// Dense-coalesced version: one float4 per thread, block-of-8 max shared
// between adjacent (even, odd) lanes via shfl.xor.1. Warp requests are 512B
// dense -> 4 L1 wavefronts per LDG/STG instead of 8 (R1's 32B-stride layout).
// R2/R3 containers flaked; this resubmission drops the __ldcs/__stcs hints
// (the secondary lever) to minimize exotic surface while measuring the
// coalescing effect cleanly.

#define COLS 12284
#define F4_PER_ROW 3071          // 12284 / 4 (odd -> one idle thread per row)

__device__ __forceinline__ float qdq(float v, float recip, float step) {
    float q = rintf(v * recip);            // round-half-to-even, matches jnp.round
    q = fminf(fmaxf(q, -128.0f), 127.0f);  // clip to [-2^7, 2^7-1]
    return q * step;
}

__global__ __launch_bounds__(256) void bfp_quant_kernel(
    const float4* __restrict__ x, float4* __restrict__ out)
{
    const int f = blockIdx.x * 256 + threadIdx.x;          // float4 idx in row, 0..3071
    const long long idx = (long long)blockIdx.y * F4_PER_ROW + f;
    const bool valid = (f < F4_PER_ROW);

    float4 a;
    if (valid) {
        a = x[idx];
    } else {
        a.x = a.y = a.z = a.w = 0.0f;      // tail pad: zeros never raise maxabs
    }

    // per-float4 maxabs, then combine with pair lane (the other half of the
    // block of 8). Even lane holds elements 0-3 of the block, odd lane 4-7.
    float m = fmaxf(fmaxf(fabsf(a.x), fabsf(a.y)), fmaxf(fabsf(a.z), fabsf(a.w)));
    m = fmaxf(m, __shfl_xor_sync(0xffffffffu, m, 1));

    // maxabs = frac * 2^e, frac in [0.5, 1). step = 2^(e-7).
    // m == 0 -> frexpf gives e = 0 -> q = 0 -> output 0. Exact.
    int e;
    frexpf(m, &e);
    const float step  = ldexpf(1.0f, e - 7);   // exact power of two
    const float recip = ldexpf(1.0f, 7 - e);   // exact reciprocal

    float4 o;
    o.x = qdq(a.x, recip, step);
    o.y = qdq(a.y, recip, step);
    o.z = qdq(a.z, recip, step);
    o.w = qdq(a.w, recip, step);

    if (valid) {
        out[idx] = o;
    }
}

extern "C" void kernel_launch(void* const* d_in, const int* in_sizes, int n_in,
                              void* d_out, int out_size) {
    const float4* x = (const float4*)d_in[0];
    float4* out = (float4*)d_out;
    const int nrows = in_sizes[0] / COLS;          // 8192 for the reference shape

    // 12 CTAs x 256 threads = 3072 threads/row covers 3071 float4s (+1 idle)
    dim3 grid((F4_PER_ROW + 255) / 256, nrows);    // (12, 8192)
    bfp_quant_kernel<<<grid, 256>>>(x, out);
}

// round 5
// speedup vs baseline: 1.0946x; 1.0946x over previous
#include <cuda_runtime.h>
#include <cuda_bf16.h>

// BFP quant-dequant: shared 8-bit exponent per block of 8 along the last dim.
// x: [8192, 12284] fp32 -> out same shape.
//
// R5: dense-coalesced, 4 float4s per thread at warp-stride spacing (MLP=4,
// every warp request 512B dense), pair-lane shfl for block-of-8 max, and
// bit-trick shared-exponent math (no frexpf/ldexpf).

#define COLS 12284
#define F4_PER_ROW 3071          // 12284 / 4
// padded to 3072 slots/row; warp covers 128 slots; 24 warps = 3 CTAs x 8 warps

__device__ __forceinline__ float qdq(float v, float recip, float step) {
    float q = rintf(v * recip);            // round-half-to-even, matches jnp.round
    q = fminf(fmaxf(q, -128.0f), 127.0f);  // clip to [-2^7, 2^7-1]
    return q * step;
}

__device__ __forceinline__ float f4maxabs(float4 a) {
    return fmaxf(fmaxf(fabsf(a.x), fabsf(a.y)), fmaxf(fabsf(a.z), fabsf(a.w)));
}

// block max m -> exact power-of-two (recip, step), matching frexp semantics:
// step = 2^(eb-133) = 2^(floor(log2 m) - 7), recip = 1/step. eb clamped >= 7
// so m == 0 (or absurd denormals) degrades to exact-zero output, never inf/nan.
__device__ __forceinline__ void exp_from_max(float m, float& recip, float& step) {
    unsigned eb = __float_as_uint(m) >> 23;     // m >= 0, no sign bit
    eb = (eb < 7u) ? 7u : eb;
    recip = __uint_as_float((260u - eb) << 23); // 2^(133-eb)
    step  = __uint_as_float((eb - 6u) << 23);   // 2^(eb-133)
}

__device__ __forceinline__ float4 qdq4(float4 a, float recip, float step) {
    float4 o;
    o.x = qdq(a.x, recip, step);
    o.y = qdq(a.y, recip, step);
    o.z = qdq(a.z, recip, step);
    o.w = qdq(a.w, recip, step);
    return o;
}

__global__ __launch_bounds__(256) void bfp_quant_kernel(
    const float4* __restrict__ x, float4* __restrict__ out)
{
    const int lane = threadIdx.x & 31;
    const int warp_in_row = blockIdx.x * 8 + (threadIdx.x >> 5);   // 0..23
    const int wb = warp_in_row * 128;                              // slot base
    const long long rowbase = (long long)blockIdx.y * F4_PER_ROW;

    const int s0 = wb + lane;          // max 2975 -> always valid
    const int s1 = wb + 32 + lane;     // max 3007 -> always valid
    const int s2 = wb + 64 + lane;     // max 3039 -> always valid
    const int s3 = wb + 96 + lane;     // max 3071 -> one invalid slot (pad)
    const bool v3 = (s3 < F4_PER_ROW);

    float4 a0 = __ldcs(x + rowbase + s0);
    float4 a1 = __ldcs(x + rowbase + s1);
    float4 a2 = __ldcs(x + rowbase + s2);
    float4 a3;
    if (v3) a3 = __ldcs(x + rowbase + s3);
    else    { a3.x = a3.y = a3.z = a3.w = 0.0f; }   // zeros never raise pair max

    // block-of-8 = (even slot, odd slot) = lane pair (L, L^1) within each group
    float m0 = f4maxabs(a0), m1 = f4maxabs(a1), m2 = f4maxabs(a2), m3 = f4maxabs(a3);
    m0 = fmaxf(m0, __shfl_xor_sync(0xffffffffu, m0, 1));
    m1 = fmaxf(m1, __shfl_xor_sync(0xffffffffu, m1, 1));
    m2 = fmaxf(m2, __shfl_xor_sync(0xffffffffu, m2, 1));
    m3 = fmaxf(m3, __shfl_xor_sync(0xffffffffu, m3, 1));

    float r0, t0, r1, t1, r2, t2, r3, t3;
    exp_from_max(m0, r0, t0);
    exp_from_max(m1, r1, t1);
    exp_from_max(m2, r2, t2);
    exp_from_max(m3, r3, t3);

    __stcs(out + rowbase + s0, qdq4(a0, r0, t0));
    __stcs(out + rowbase + s1, qdq4(a1, r1, t1));
    __stcs(out + rowbase + s2, qdq4(a2, r2, t2));
    if (v3) __stcs(out + rowbase + s3, qdq4(a3, r3, t3));
}

extern "C" void kernel_launch(void* const* d_in, const int* in_sizes, int n_in,
                              void* d_out, int out_size) {
    const float4* x = (const float4*)d_in[0];
    float4* out = (float4*)d_out;
    const int nrows = in_sizes[0] / COLS;      // 8192 for the reference shape

    dim3 grid(3, nrows);                       // 3 CTAs x 8 warps x 128 slots = 3072/row
    bfp_quant_kernel<<<grid, 256>>>(x, out);
}